// round 10
// baseline (speedup 1.0000x reference)
#include <cuda_runtime.h>

#define NMAX 50176
#define EMAX 800064
#define FEAT 32
#define HID  64

typedef unsigned long long ull;

// ---------------- scratch (device globals; no allocation allowed) ----------
__device__ __align__(16)  float g_do_inv[NMAX];
__device__ __align__(16)  float g_di_inv[NMAX];
__device__ __align__(16)  float g_dis[NMAX];
__device__ __align__(16)  int   g_ccnt[NMAX];
__device__ __align__(16)  int   g_rcnt[NMAX];
__device__ __align__(16)  int   g_coff[NMAX + 1];
__device__ __align__(16)  int   g_roff[NMAX + 1];
__device__ __align__(16)  int   g_ccur[NMAX];
__device__ __align__(16)  int   g_rcur[NMAX];
__device__ __align__(16)  ull   g_cpay[EMAX];   // (f32 weight_out bits << 32) | src row r
__device__ __align__(16)  ull   g_rpay[EMAX];   // (f32 weight_in  bits << 32) | src col c
__device__ __align__(128) float g_P1o[NMAX * FEAT];
__device__ __align__(128) float g_P1i[NMAX * FEAT];
__device__ __align__(128) float g_P2o[NMAX * FEAT];
__device__ __align__(128) float g_P2i[NMAX * FEAT];
__device__ __align__(256) float g_H[NMAX * HID];
__device__ __align__(256) float g_xw[NMAX * HID];
__device__ __align__(256) float g_y[NMAX * HID];
__device__ __align__(16)  float g_Wcat[160 * 128];
__device__ __align__(16)  float g_bcat[128];
__device__ float g_S[HID];
__device__ float g_SS[HID];

// ---------------- helpers ----------------
__device__ __forceinline__ float sigm(float z) { return 1.0f / (1.0f + expf(-z)); }

__device__ __forceinline__ ull pk(float lo, float hi) {
    ull r; asm("mov.b64 %0, {%1, %2};" : "=l"(r) : "f"(lo), "f"(hi)); return r;
}
__device__ __forceinline__ float2 upk(ull v) {
    float2 r; asm("mov.b64 {%0, %1}, %2;" : "=f"(r.x), "=f"(r.y) : "l"(v)); return r;
}
__device__ __forceinline__ void fma2(ull& d, ull a, ull b) {
    asm("fma.rn.f32x2 %0, %1, %2, %0;" : "+l"(d) : "l"(a), "l"(b));
}

// ---------------- kernels ----------------

__global__ void k_zero(int n) {
    int i = blockIdx.x * blockDim.x + threadIdx.x;
    if (i < n) {
        g_do_inv[i] = 0.f; g_di_inv[i] = 0.f;
        g_ccnt[i] = 0; g_rcnt[i] = 0;
    }
    if (i < HID) { g_S[i] = 0.f; g_SS[i] = 0.f; }
}

// build fused 160x128 gate weight
__global__ void k_wcat(const float* __restrict__ Wz, const float* __restrict__ Wh,
                       const float* __restrict__ bz, const float* __restrict__ bh) {
    int idx = blockIdx.x * blockDim.x + threadIdx.x;
    if (idx < 160 * 128) {
        int k5 = idx >> 7;
        int j  = idx & 127;
        int b = k5 >> 5;
        int f = k5 & 31;
        const float* Wg = (j < 64) ? Wz : Wh;
        int jj = j & 63;
        float v;
        if (b == 0) {
            v = Wg[((0 * 3 + 0) * 96 + f) * 64 + jj] + Wg[((1 * 3 + 0) * 96 + f) * 64 + jj];
        } else {
            int d = (b <= 2) ? 0 : 1;
            int k = (b <= 2) ? b : (b - 2);
            v = Wg[((d * 3 + k) * 96 + f) * 64 + jj];
        }
        g_Wcat[idx] = v;
    } else if (idx < 160 * 128 + 128) {
        int j = idx - 160 * 128;
        g_bcat[j] = (j < 64) ? bz[j] : bh[j - 64];
    }
}

// weighted degrees + CSR bin counts
__global__ void k_deg(const int* __restrict__ row, const int* __restrict__ col,
                      const float* __restrict__ ew, int E) {
    int e = blockIdx.x * blockDim.x + threadIdx.x;
    if (e >= E) return;
    int r = row[e], c = col[e];
    float w = ew[e];
    atomicAdd(&g_do_inv[r], w);
    atomicAdd(&g_di_inv[c], w);
    atomicAdd(&g_ccnt[c], 1);
    atomicAdd(&g_rcnt[r], 1);
}

// exclusive prefix scan of bin counts -> offsets + cursors; block 0 also
// performs the degree-inverse / dis computation (k_inv folded in).
// blockIdx.x == 0: ccnt -> coff/ccur ; 1: rcnt -> roff/rcur.
__global__ void __launch_bounds__(1024) k_scan(int n) {
    const int T = 1024;
    int tid = threadIdx.x;
    if (blockIdx.x == 0) {
        for (int i = tid; i < n; i += T) {
            float a = g_do_inv[i];
            g_do_inv[i] = (a > 0.f) ? (1.0f / a) : 0.f;
            float b = g_di_inv[i];
            g_di_inv[i] = (b > 0.f) ? (1.0f / b) : 0.f;
            g_dis[i] = rsqrtf((float)g_ccnt[i] + 1.0f);
        }
    }
    int* cnt = blockIdx.x ? g_rcnt : g_ccnt;
    int* off = blockIdx.x ? g_roff : g_coff;
    int* cur = blockIdx.x ? g_rcur : g_ccur;
    int chunk = (n + T - 1) / T;
    int s0 = tid * chunk;
    int s1 = min(s0 + chunk, n);
    int s = 0;
    for (int i = s0; i < s1; i++) s += cnt[i];
    __shared__ int sm[T];
    sm[tid] = s;
    __syncthreads();
    for (int o = 1; o < T; o <<= 1) {
        int v = (tid >= o) ? sm[tid - o] : 0;
        __syncthreads();
        sm[tid] += v;
        __syncthreads();
    }
    int run = (tid == 0) ? 0 : sm[tid - 1];
    for (int i = s0; i < s1; i++) { off[i] = run; cur[i] = run; run += cnt[i]; }
    if (tid == T - 1) off[n] = run;   // == E
}

// place each edge payload into its dest bin (order within bin irrelevant)
__global__ void k_fill(const int* __restrict__ row, const int* __restrict__ col,
                       const float* __restrict__ ew, int E) {
    int e = blockIdx.x * blockDim.x + threadIdx.x;
    if (e >= E) return;
    int r = row[e], c = col[e];
    float w = ew[e];
    float wo = w * g_do_inv[r];
    float wi = w * g_di_inv[c];
    int p = atomicAdd(&g_ccur[c], 1);
    g_cpay[p] = ((ull)__float_as_uint(wo) << 32) | (unsigned)r;
    int p2 = atomicAdd(&g_rcur[r], 1);
    g_rpay[p2] = ((ull)__float_as_uint(wi) << 32) | (unsigned)c;
}

// diffusion hop as atomic-free gather, software-pipelined 4 edges/iteration
// for MLP (the serial payload->row dependent chain was the R9 regression).
// warp per (node,dir); lane = feature.
__global__ void k_spmm_g(const float* __restrict__ x, int hop, int n) {
    int t = blockIdx.x * blockDim.x + threadIdx.x;
    int wg = t >> 5;
    int lane = t & 31;
    if (wg >= 2 * n) return;
    int node = wg >> 1;
    int dir = wg & 1;
    const float* src;
    float* dst;
    const ull* pay;
    const int* off;
    if (dir == 0) { src = (hop == 1) ? x : g_P1o; dst = (hop == 1) ? g_P1o : g_P2o; pay = g_cpay; off = g_coff; }
    else          { src = (hop == 1) ? x : g_P1i; dst = (hop == 1) ? g_P1i : g_P2i; pay = g_rpay; off = g_roff; }
    int b0 = off[node], b1 = off[node + 1];
    float acc = 0.f;
    int i = b0;
    for (; i + 4 <= b1; i += 4) {
        ull p0 = pay[i];
        ull p1 = pay[i + 1];
        ull p2 = pay[i + 2];
        ull p3 = pay[i + 3];
        int s0 = (int)(unsigned)(p0 & 0xffffffffu);
        int s1 = (int)(unsigned)(p1 & 0xffffffffu);
        int s2 = (int)(unsigned)(p2 & 0xffffffffu);
        int s3 = (int)(unsigned)(p3 & 0xffffffffu);
        float v0 = src[s0 * FEAT + lane];
        float v1 = src[s1 * FEAT + lane];
        float v2 = src[s2 * FEAT + lane];
        float v3 = src[s3 * FEAT + lane];
        acc = fmaf(__uint_as_float((unsigned)(p0 >> 32)), v0, acc);
        acc = fmaf(__uint_as_float((unsigned)(p1 >> 32)), v1, acc);
        acc = fmaf(__uint_as_float((unsigned)(p2 >> 32)), v2, acc);
        acc = fmaf(__uint_as_float((unsigned)(p3 >> 32)), v3, acc);
    }
    for (; i < b1; i++) {
        ull p = pay[i];
        int s = (int)(unsigned)(p & 0xffffffffu);
        acc = fmaf(__uint_as_float((unsigned)(p >> 32)), src[s * FEAT + lane], acc);
    }
    dst[node * FEAT + lane] = acc;
}

// fused gate GEMM (f32x2): [x|P1o|P2o|P1i|P2i](Nx160) @ Wcat(160x128)+bcat,
// H = (1-sigmoid(Zd))*tanh(Hd); gate halves exchanged via shfl_xor(16).
__global__ void __launch_bounds__(128) k_gates(const float* __restrict__ x, int n) {
    __shared__ ull p2s[32 * 160];  // 40 KB
    int tid = threadIdx.x;
    int n0 = blockIdx.x * 32;

    for (int idx = tid; idx < 32 * 160; idx += 128) {
        int m = idx / 160;
        int k = idx - m * 160;
        int node = n0 + m;
        float v = 0.f;
        if (node < n) {
            int b = k >> 5, f = k & 31;
            const float* src = (b == 0) ? x : (b == 1) ? g_P1o : (b == 2) ? g_P2o
                             : (b == 3) ? g_P1i : g_P2i;
            v = src[node * FEAT + f];
        }
        p2s[idx] = pk(v, v);
    }
    __syncthreads();

    int w = tid >> 5, j = tid & 31;
    int m0 = w * 8;

    ull acc[8][2];
    float4 bv = *reinterpret_cast<const float4*>(&g_bcat[4 * j]);
    ull b01 = pk(bv.x, bv.y), b23 = pk(bv.z, bv.w);
#pragma unroll
    for (int m = 0; m < 8; m++) { acc[m][0] = b01; acc[m][1] = b23; }

    const ulonglong2* Wm = reinterpret_cast<const ulonglong2*>(g_Wcat);
    for (int k = 0; k < 160; k++) {
        ulonglong2 wv = Wm[k * 32 + j];
#pragma unroll
        for (int m = 0; m < 8; m++) {
            ull pv = p2s[(m0 + m) * 160 + k];
            fma2(acc[m][0], wv.x, pv);
            fma2(acc[m][1], wv.y, pv);
        }
    }

#pragma unroll
    for (int m = 0; m < 8; m++) {
        int node = n0 + m0 + m;
        float2 a0 = upk(acc[m][0]);
        float2 a1 = upk(acc[m][1]);
        float p0 = __shfl_xor_sync(0xffffffffu, a0.x, 16);
        float p1 = __shfl_xor_sync(0xffffffffu, a0.y, 16);
        float p2 = __shfl_xor_sync(0xffffffffu, a1.x, 16);
        float p3 = __shfl_xor_sync(0xffffffffu, a1.y, 16);
        if (j < 16 && node < n) {
            float4 h;
            h.x = (1.f - sigm(a0.x)) * tanhf(p0);
            h.y = (1.f - sigm(a0.y)) * tanhf(p1);
            h.z = (1.f - sigm(a1.x)) * tanhf(p2);
            h.w = (1.f - sigm(a1.y)) * tanhf(p3);
            *reinterpret_cast<float4*>(&g_H[node * HID + 4 * j]) = h;
        }
    }
}

// xw = H @ gcn_w (f32x2). Self-term/bias handled in k_gcn_g.
__global__ void __launch_bounds__(128) k_xw(const float* __restrict__ gcn_w, int n) {
    __shared__ ull h2s[32 * 64];
    int tid = threadIdx.x;
    int n0 = blockIdx.x * 32;

    for (int idx = tid; idx < 32 * 64; idx += 128) {
        int m = idx >> 6, k = idx & 63;
        int node = n0 + m;
        float v = (node < n) ? g_H[node * HID + k] : 0.f;
        h2s[idx] = pk(v, v);
    }
    __syncthreads();

    int w = tid >> 5, j = tid & 31;
    int m0 = w * 8;

    ull acc[8];
#pragma unroll
    for (int m = 0; m < 8; m++) acc[m] = 0ull;

    for (int k = 0; k < 64; k++) {
        ull wv = *reinterpret_cast<const ull*>(&gcn_w[k * 64 + 2 * j]);
#pragma unroll
        for (int m = 0; m < 8; m++) {
            fma2(acc[m], wv, h2s[(m0 + m) * 64 + k]);
        }
    }

#pragma unroll
    for (int m = 0; m < 8; m++) {
        int node = n0 + m0 + m;
        if (node < n) {
            float2 a = upk(acc[m]);
            *reinterpret_cast<float2*>(&g_xw[node * HID + 2 * j]) = a;
        }
    }
}

// GCN gather, software-pipelined 2 edges/iteration (4 independent row loads).
// warp per node c; lane handles channels lane and lane+32.
// y[c] = dis[c]^2*xw[c] + gcn_b + sum_in-edges dis[r]*dis[c]*xw[r]
__global__ void k_gcn_g(const float* __restrict__ gcn_b, int n) {
    int t = blockIdx.x * blockDim.x + threadIdx.x;
    int c = t >> 5;
    int lane = t & 31;
    if (c >= n) return;
    float dc = g_dis[c];
    float d2 = dc * dc;
    float a0 = fmaf(d2, g_xw[c * HID + lane],      gcn_b[lane]);
    float a1 = fmaf(d2, g_xw[c * HID + lane + 32], gcn_b[lane + 32]);
    int b0 = g_coff[c], b1 = g_coff[c + 1];
    int i = b0;
    for (; i + 2 <= b1; i += 2) {
        ull p0 = g_cpay[i];
        ull p1 = g_cpay[i + 1];
        int r0 = (int)(unsigned)(p0 & 0xffffffffu);
        int r1 = (int)(unsigned)(p1 & 0xffffffffu);
        float n0 = g_dis[r0] * dc;
        float n1 = g_dis[r1] * dc;
        float u00 = g_xw[r0 * HID + lane];
        float u01 = g_xw[r0 * HID + lane + 32];
        float u10 = g_xw[r1 * HID + lane];
        float u11 = g_xw[r1 * HID + lane + 32];
        a0 = fmaf(n0, u00, a0);
        a1 = fmaf(n0, u01, a1);
        a0 = fmaf(n1, u10, a0);
        a1 = fmaf(n1, u11, a1);
    }
    for (; i < b1; i++) {
        ull p = g_cpay[i];
        int r = (int)(unsigned)(p & 0xffffffffu);
        float nrm = g_dis[r] * dc;
        a0 = fmaf(nrm, g_xw[r * HID + lane],      a0);
        a1 = fmaf(nrm, g_xw[r * HID + lane + 32], a1);
    }
    g_y[c * HID + lane]      = a0;
    g_y[c * HID + lane + 32] = a1;
}

// per-channel sums of relu(y) and relu(y)^2
__global__ void k_stats(int n) {
    int tid = threadIdx.x;
    int c = tid & 63;
    int rg = tid >> 6;
    float s = 0.f, ss = 0.f;
    for (int r = blockIdx.x * 4 + rg; r < n; r += gridDim.x * 4) {
        float v = g_y[r * HID + c];
        v = fmaxf(v, 0.f);
        s += v;
        ss += v * v;
    }
    __shared__ float sm1[256], sm2[256];
    sm1[tid] = s; sm2[tid] = ss;
    __syncthreads();
    if (tid < 64) {
        s  = sm1[tid] + sm1[tid + 64] + sm1[tid + 128] + sm1[tid + 192];
        ss = sm2[tid] + sm2[tid + 64] + sm2[tid + 128] + sm2[tid + 192];
        atomicAdd(&g_S[c], s);
        atomicAdd(&g_SS[c], ss);
    }
}

// out[n] = dot(relu(y[n,:]), coef) + cnst, with BN+linear fold computed
// inline per warp from g_S/g_SS (all 64-wide arrays are L1-resident
// broadcasts; constant term folds into the existing warp reduction).
__global__ void k_out(const float* __restrict__ gamma, const float* __restrict__ beta,
                      const float* __restrict__ lw, const float* __restrict__ lb,
                      float* __restrict__ out, int n) {
    int t = blockIdx.x * blockDim.x + threadIdx.x;
    int node = t >> 5;
    int j = t & 31;
    if (node >= n) return;
    float invn = 1.0f / (float)n;
    int j1 = j + 32;
    float m0 = g_S[j]  * invn,            m1 = g_S[j1] * invn;
    float v0 = g_SS[j] * invn - m0 * m0,  v1 = g_SS[j1] * invn - m1 * m1;
    float a0 = gamma[j]  * rsqrtf(v0 + 1e-5f);
    float a1 = gamma[j1] * rsqrtf(v1 + 1e-5f);
    float w0 = lw[j], w1 = lw[j1];
    float c0 = a0 * w0, c1 = a1 * w1;
    float part = (beta[j] - m0 * a0) * w0 + (beta[j1] - m1 * a1) * w1;
    float acc = fmaxf(g_y[node * HID + j],  0.f) * c0
              + fmaxf(g_y[node * HID + j1], 0.f) * c1
              + part;
#pragma unroll
    for (int o = 16; o > 0; o >>= 1) acc += __shfl_down_sync(0xffffffffu, acc, o);
    if (j == 0) out[node] = acc + lb[0];
}

// ---------------- launch ----------------
extern "C" void kernel_launch(void* const* d_in, const int* in_sizes, int n_in,
                              void* d_out, int out_size) {
    const float* x     = (const float*)d_in[0];
    const int*   ei    = (const int*)d_in[1];
    const float* ew    = (const float*)d_in[2];
    const float* Wz    = (const float*)d_in[3];
    const float* bz    = (const float*)d_in[4];
    const float* Wh    = (const float*)d_in[7];
    const float* bh    = (const float*)d_in[8];
    const float* gcn_w = (const float*)d_in[9];
    const float* gcn_b = (const float*)d_in[10];
    const float* gamma = (const float*)d_in[11];
    const float* beta  = (const float*)d_in[12];
    const float* lw    = (const float*)d_in[13];
    const float* lb    = (const float*)d_in[14];
    float* out = (float*)d_out;

    int n = in_sizes[0] / FEAT;
    int E = in_sizes[2];
    const int* row = ei;
    const int* col = ei + E;

    k_zero<<<(n + 255) / 256, 256>>>(n);
    k_wcat<<<(160 * 128 + 128 + 255) / 256, 256>>>(Wz, Wh, bz, bh);
    k_deg<<<(E + 255) / 256, 256>>>(row, col, ew, E);
    k_scan<<<2, 1024>>>(n);   // includes degree-inverse (k_inv folded in)
    k_fill<<<(E + 255) / 256, 256>>>(row, col, ew, E);
    // hop 1 (both dirs), hop 2 (both dirs) — pipelined atomic-free gathers
    k_spmm_g<<<(2 * n * 32 + 255) / 256, 256>>>(x, 1, n);
    k_spmm_g<<<(2 * n * 32 + 255) / 256, 256>>>(x, 2, n);
    // fused gates -> H
    k_gates<<<(n + 31) / 32, 128>>>(x, n);
    // GCN dense
    k_xw<<<(n + 31) / 32, 128>>>(gcn_w, n);
    // GCN gather (self term + bias fused)
    k_gcn_g<<<(n * 32 + 255) / 256, 256>>>(gcn_b, n);
    // BN stats + fused fold/output
    k_stats<<<512, 256>>>(n);
    k_out<<<(n * 32 + 255) / 256, 256>>>(gamma, beta, lw, lb, out, n);
}

// round 11
// speedup vs baseline: 1.4089x; 1.4089x over previous
#include <cuda_runtime.h>

#define NMAX 50176
#define EMAX 800064
#define FEAT 32
#define HID  64

typedef unsigned long long ull;

// ---------------- scratch (device globals; no allocation allowed) ----------
__device__ __align__(16)  float g_do_inv[NMAX];
__device__ __align__(16)  float g_di_inv[NMAX];
__device__ __align__(16)  float g_dis[NMAX];
__device__ __align__(16)  int   g_ccnt[NMAX];
__device__ __align__(16)  int   g_rcnt[NMAX];
__device__ __align__(16)  int   g_coff[NMAX + 1];
__device__ __align__(16)  int   g_roff[NMAX + 1];
__device__ __align__(16)  int   g_ccur[NMAX];
__device__ __align__(16)  int   g_rcur[NMAX];
__device__ __align__(16)  int   g_bsum[2 * 512];   // per-tile sums (exclusive-scanned in place)
__device__ __align__(16)  ull   g_cpay[EMAX];   // (f32 weight_out bits << 32) | src row r
__device__ __align__(16)  ull   g_rpay[EMAX];   // (f32 weight_in  bits << 32) | src col c
__device__ __align__(128) float g_P1o[NMAX * FEAT];
__device__ __align__(128) float g_P1i[NMAX * FEAT];
__device__ __align__(128) float g_P2o[NMAX * FEAT];
__device__ __align__(128) float g_P2i[NMAX * FEAT];
__device__ __align__(256) float g_H[NMAX * HID];
__device__ __align__(256) float g_xw[NMAX * HID];
__device__ __align__(256) float g_y[NMAX * HID];
__device__ __align__(16)  float g_Wcat[160 * 128];
__device__ __align__(16)  float g_bcat[128];
__device__ float g_S[HID];
__device__ float g_SS[HID];

// ---------------- helpers ----------------
__device__ __forceinline__ float sigm(float z) { return 1.0f / (1.0f + expf(-z)); }

__device__ __forceinline__ ull pk(float lo, float hi) {
    ull r; asm("mov.b64 %0, {%1, %2};" : "=l"(r) : "f"(lo), "f"(hi)); return r;
}
__device__ __forceinline__ float2 upk(ull v) {
    float2 r; asm("mov.b64 {%0, %1}, %2;" : "=f"(r.x), "=f"(r.y) : "l"(v)); return r;
}
__device__ __forceinline__ void fma2(ull& d, ull a, ull b) {
    asm("fma.rn.f32x2 %0, %1, %2, %0;" : "+l"(d) : "l"(a), "l"(b));
}

// ---------------- kernels ----------------

__global__ void k_zero(int n) {
    int i = blockIdx.x * blockDim.x + threadIdx.x;
    if (i < n) {
        g_do_inv[i] = 0.f; g_di_inv[i] = 0.f;
        g_ccnt[i] = 0; g_rcnt[i] = 0;
    }
    if (i < HID) { g_S[i] = 0.f; g_SS[i] = 0.f; }
}

// build fused 160x128 gate weight
__global__ void k_wcat(const float* __restrict__ Wz, const float* __restrict__ Wh,
                       const float* __restrict__ bz, const float* __restrict__ bh) {
    int idx = blockIdx.x * blockDim.x + threadIdx.x;
    if (idx < 160 * 128) {
        int k5 = idx >> 7;
        int j  = idx & 127;
        int b = k5 >> 5;
        int f = k5 & 31;
        const float* Wg = (j < 64) ? Wz : Wh;
        int jj = j & 63;
        float v;
        if (b == 0) {
            v = Wg[((0 * 3 + 0) * 96 + f) * 64 + jj] + Wg[((1 * 3 + 0) * 96 + f) * 64 + jj];
        } else {
            int d = (b <= 2) ? 0 : 1;
            int k = (b <= 2) ? b : (b - 2);
            v = Wg[((d * 3 + k) * 96 + f) * 64 + jj];
        }
        g_Wcat[idx] = v;
    } else if (idx < 160 * 128 + 128) {
        int j = idx - 160 * 128;
        g_bcat[j] = (j < 64) ? bz[j] : bh[j - 64];
    }
}

// weighted degrees + CSR bin counts
__global__ void k_deg(const int* __restrict__ row, const int* __restrict__ col,
                      const float* __restrict__ ew, int E) {
    int e = blockIdx.x * blockDim.x + threadIdx.x;
    if (e >= E) return;
    int r = row[e], c = col[e];
    float w = ew[e];
    atomicAdd(&g_do_inv[r], w);
    atomicAdd(&g_di_inv[c], w);
    atomicAdd(&g_ccnt[c], 1);
    atomicAdd(&g_rcnt[r], 1);
}

// ---- parallel 3-phase scan (replaces the 2-block k_scan that ncu showed
// eating 146us at 2/148 SM occupancy) ----

// phase 1: per-256-tile sums. grid = 2*NB; blocks [0,NB) -> ccnt, [NB,2NB) -> rcnt.
__global__ void k_bsum(int n, int NB) {
    int arr = (blockIdx.x >= NB) ? 1 : 0;
    int b = blockIdx.x - arr * NB;
    const int* cnt = arr ? g_rcnt : g_ccnt;
    int t = threadIdx.x;
    int i = b * 256 + t;
    int v = (i < n) ? cnt[i] : 0;
#pragma unroll
    for (int o = 16; o > 0; o >>= 1) v += __shfl_down_sync(0xffffffffu, v, o);
    __shared__ int sm[8];
    if ((t & 31) == 0) sm[t >> 5] = v;
    __syncthreads();
    if (t == 0) {
        int s = 0;
#pragma unroll
        for (int q = 0; q < 8; q++) s += sm[q];
        g_bsum[arr * 512 + b] = s;
    }
}

// phase 2: single block exclusive-scans the NB tile sums of BOTH arrays (NB<=256).
__global__ void __launch_bounds__(256) k_bscan(int NB) {
    __shared__ int sm0[256], sm1[256];
    int t = threadIdx.x;
    sm0[t] = (t < NB) ? g_bsum[t] : 0;
    sm1[t] = (t < NB) ? g_bsum[512 + t] : 0;
    __syncthreads();
    for (int o = 1; o < 256; o <<= 1) {
        int v0 = (t >= o) ? sm0[t - o] : 0;
        int v1 = (t >= o) ? sm1[t - o] : 0;
        __syncthreads();
        sm0[t] += v0; sm1[t] += v1;
        __syncthreads();
    }
    if (t < NB) {
        g_bsum[t]       = (t == 0) ? 0 : sm0[t - 1];
        g_bsum[512 + t] = (t == 0) ? 0 : sm1[t - 1];
    }
}

// phase 3: per-tile 256-wide scan + base -> off/cur. Col-array blocks also
// compute the degree inverses / dis (old k_inv folded here).
__global__ void k_off(int n, int NB) {
    int arr = (blockIdx.x >= NB) ? 1 : 0;
    int b = blockIdx.x - arr * NB;
    const int* cnt = arr ? g_rcnt : g_ccnt;
    int* off = arr ? g_roff : g_coff;
    int* cur = arr ? g_rcur : g_ccur;
    int base = g_bsum[arr * 512 + b];
    int t = threadIdx.x;
    int i = b * 256 + t;
    if (arr == 0 && i < n) {
        float a = g_do_inv[i];
        g_do_inv[i] = (a > 0.f) ? (1.0f / a) : 0.f;
        float d = g_di_inv[i];
        g_di_inv[i] = (d > 0.f) ? (1.0f / d) : 0.f;
        g_dis[i] = rsqrtf((float)g_ccnt[i] + 1.0f);
    }
    __shared__ int sm[256];
    int v = (i < n) ? cnt[i] : 0;
    sm[t] = v;
    __syncthreads();
    for (int o = 1; o < 256; o <<= 1) {
        int u = (t >= o) ? sm[t - o] : 0;
        __syncthreads();
        sm[t] += u;
        __syncthreads();
    }
    int excl = base + sm[t] - v;
    if (i < n) { off[i] = excl; cur[i] = excl; }
    if (i == n - 1) off[n] = excl + v;
}

// place each edge payload into its dest bin (order within bin irrelevant)
__global__ void k_fill(const int* __restrict__ row, const int* __restrict__ col,
                       const float* __restrict__ ew, int E) {
    int e = blockIdx.x * blockDim.x + threadIdx.x;
    if (e >= E) return;
    int r = row[e], c = col[e];
    float w = ew[e];
    float wo = w * g_do_inv[r];
    float wi = w * g_di_inv[c];
    int p = atomicAdd(&g_ccur[c], 1);
    g_cpay[p] = ((ull)__float_as_uint(wo) << 32) | (unsigned)r;
    int p2 = atomicAdd(&g_rcur[r], 1);
    g_rpay[p2] = ((ull)__float_as_uint(wi) << 32) | (unsigned)c;
}

// diffusion hop as atomic-free gather, software-pipelined 4 edges/iteration.
// warp per (node,dir); lane = feature.
__global__ void k_spmm_g(const float* __restrict__ x, int hop, int n) {
    int t = blockIdx.x * blockDim.x + threadIdx.x;
    int wg = t >> 5;
    int lane = t & 31;
    if (wg >= 2 * n) return;
    int node = wg >> 1;
    int dir = wg & 1;
    const float* src;
    float* dst;
    const ull* pay;
    const int* off;
    if (dir == 0) { src = (hop == 1) ? x : g_P1o; dst = (hop == 1) ? g_P1o : g_P2o; pay = g_cpay; off = g_coff; }
    else          { src = (hop == 1) ? x : g_P1i; dst = (hop == 1) ? g_P1i : g_P2i; pay = g_rpay; off = g_roff; }
    int b0 = off[node], b1 = off[node + 1];
    float acc = 0.f;
    int i = b0;
    for (; i + 4 <= b1; i += 4) {
        ull p0 = pay[i];
        ull p1 = pay[i + 1];
        ull p2 = pay[i + 2];
        ull p3 = pay[i + 3];
        int s0 = (int)(unsigned)(p0 & 0xffffffffu);
        int s1 = (int)(unsigned)(p1 & 0xffffffffu);
        int s2 = (int)(unsigned)(p2 & 0xffffffffu);
        int s3 = (int)(unsigned)(p3 & 0xffffffffu);
        float v0 = src[s0 * FEAT + lane];
        float v1 = src[s1 * FEAT + lane];
        float v2 = src[s2 * FEAT + lane];
        float v3 = src[s3 * FEAT + lane];
        acc = fmaf(__uint_as_float((unsigned)(p0 >> 32)), v0, acc);
        acc = fmaf(__uint_as_float((unsigned)(p1 >> 32)), v1, acc);
        acc = fmaf(__uint_as_float((unsigned)(p2 >> 32)), v2, acc);
        acc = fmaf(__uint_as_float((unsigned)(p3 >> 32)), v3, acc);
    }
    for (; i < b1; i++) {
        ull p = pay[i];
        int s = (int)(unsigned)(p & 0xffffffffu);
        acc = fmaf(__uint_as_float((unsigned)(p >> 32)), src[s * FEAT + lane], acc);
    }
    dst[node * FEAT + lane] = acc;
}

// fused gate GEMM (f32x2): [x|P1o|P2o|P1i|P2i](Nx160) @ Wcat(160x128)+bcat,
// H = (1-sigmoid(Zd))*tanh(Hd); gate halves exchanged via shfl_xor(16).
__global__ void __launch_bounds__(128) k_gates(const float* __restrict__ x, int n) {
    __shared__ ull p2s[32 * 160];  // 40 KB
    int tid = threadIdx.x;
    int n0 = blockIdx.x * 32;

    for (int idx = tid; idx < 32 * 160; idx += 128) {
        int m = idx / 160;
        int k = idx - m * 160;
        int node = n0 + m;
        float v = 0.f;
        if (node < n) {
            int b = k >> 5, f = k & 31;
            const float* src = (b == 0) ? x : (b == 1) ? g_P1o : (b == 2) ? g_P2o
                             : (b == 3) ? g_P1i : g_P2i;
            v = src[node * FEAT + f];
        }
        p2s[idx] = pk(v, v);
    }
    __syncthreads();

    int w = tid >> 5, j = tid & 31;
    int m0 = w * 8;

    ull acc[8][2];
    float4 bv = *reinterpret_cast<const float4*>(&g_bcat[4 * j]);
    ull b01 = pk(bv.x, bv.y), b23 = pk(bv.z, bv.w);
#pragma unroll
    for (int m = 0; m < 8; m++) { acc[m][0] = b01; acc[m][1] = b23; }

    const ulonglong2* Wm = reinterpret_cast<const ulonglong2*>(g_Wcat);
    for (int k = 0; k < 160; k++) {
        ulonglong2 wv = Wm[k * 32 + j];
#pragma unroll
        for (int m = 0; m < 8; m++) {
            ull pv = p2s[(m0 + m) * 160 + k];
            fma2(acc[m][0], wv.x, pv);
            fma2(acc[m][1], wv.y, pv);
        }
    }

#pragma unroll
    for (int m = 0; m < 8; m++) {
        int node = n0 + m0 + m;
        float2 a0 = upk(acc[m][0]);
        float2 a1 = upk(acc[m][1]);
        float p0 = __shfl_xor_sync(0xffffffffu, a0.x, 16);
        float p1 = __shfl_xor_sync(0xffffffffu, a0.y, 16);
        float p2 = __shfl_xor_sync(0xffffffffu, a1.x, 16);
        float p3 = __shfl_xor_sync(0xffffffffu, a1.y, 16);
        if (j < 16 && node < n) {
            float4 h;
            h.x = (1.f - sigm(a0.x)) * tanhf(p0);
            h.y = (1.f - sigm(a0.y)) * tanhf(p1);
            h.z = (1.f - sigm(a1.x)) * tanhf(p2);
            h.w = (1.f - sigm(a1.y)) * tanhf(p3);
            *reinterpret_cast<float4*>(&g_H[node * HID + 4 * j]) = h;
        }
    }
}

// xw = H @ gcn_w (f32x2). Self-term/bias handled in k_gcn_g.
__global__ void __launch_bounds__(128) k_xw(const float* __restrict__ gcn_w, int n) {
    __shared__ ull h2s[32 * 64];
    int tid = threadIdx.x;
    int n0 = blockIdx.x * 32;

    for (int idx = tid; idx < 32 * 64; idx += 128) {
        int m = idx >> 6, k = idx & 63;
        int node = n0 + m;
        float v = (node < n) ? g_H[node * HID + k] : 0.f;
        h2s[idx] = pk(v, v);
    }
    __syncthreads();

    int w = tid >> 5, j = tid & 31;
    int m0 = w * 8;

    ull acc[8];
#pragma unroll
    for (int m = 0; m < 8; m++) acc[m] = 0ull;

    for (int k = 0; k < 64; k++) {
        ull wv = *reinterpret_cast<const ull*>(&gcn_w[k * 64 + 2 * j]);
#pragma unroll
        for (int m = 0; m < 8; m++) {
            fma2(acc[m], wv, h2s[(m0 + m) * 64 + k]);
        }
    }

#pragma unroll
    for (int m = 0; m < 8; m++) {
        int node = n0 + m0 + m;
        if (node < n) {
            float2 a = upk(acc[m]);
            *reinterpret_cast<float2*>(&g_xw[node * HID + 2 * j]) = a;
        }
    }
}

// GCN gather, software-pipelined 2 edges/iteration.
// warp per node c; lane handles channels lane and lane+32.
__global__ void k_gcn_g(const float* __restrict__ gcn_b, int n) {
    int t = blockIdx.x * blockDim.x + threadIdx.x;
    int c = t >> 5;
    int lane = t & 31;
    if (c >= n) return;
    float dc = g_dis[c];
    float d2 = dc * dc;
    float a0 = fmaf(d2, g_xw[c * HID + lane],      gcn_b[lane]);
    float a1 = fmaf(d2, g_xw[c * HID + lane + 32], gcn_b[lane + 32]);
    int b0 = g_coff[c], b1 = g_coff[c + 1];
    int i = b0;
    for (; i + 2 <= b1; i += 2) {
        ull p0 = g_cpay[i];
        ull p1 = g_cpay[i + 1];
        int r0 = (int)(unsigned)(p0 & 0xffffffffu);
        int r1 = (int)(unsigned)(p1 & 0xffffffffu);
        float n0 = g_dis[r0] * dc;
        float n1 = g_dis[r1] * dc;
        float u00 = g_xw[r0 * HID + lane];
        float u01 = g_xw[r0 * HID + lane + 32];
        float u10 = g_xw[r1 * HID + lane];
        float u11 = g_xw[r1 * HID + lane + 32];
        a0 = fmaf(n0, u00, a0);
        a1 = fmaf(n0, u01, a1);
        a0 = fmaf(n1, u10, a0);
        a1 = fmaf(n1, u11, a1);
    }
    for (; i < b1; i++) {
        ull p = g_cpay[i];
        int r = (int)(unsigned)(p & 0xffffffffu);
        float nrm = g_dis[r] * dc;
        a0 = fmaf(nrm, g_xw[r * HID + lane],      a0);
        a1 = fmaf(nrm, g_xw[r * HID + lane + 32], a1);
    }
    g_y[c * HID + lane]      = a0;
    g_y[c * HID + lane + 32] = a1;
}

// per-channel sums of relu(y) and relu(y)^2
__global__ void k_stats(int n) {
    int tid = threadIdx.x;
    int c = tid & 63;
    int rg = tid >> 6;
    float s = 0.f, ss = 0.f;
    for (int r = blockIdx.x * 4 + rg; r < n; r += gridDim.x * 4) {
        float v = g_y[r * HID + c];
        v = fmaxf(v, 0.f);
        s += v;
        ss += v * v;
    }
    __shared__ float sm1[256], sm2[256];
    sm1[tid] = s; sm2[tid] = ss;
    __syncthreads();
    if (tid < 64) {
        s  = sm1[tid] + sm1[tid + 64] + sm1[tid + 128] + sm1[tid + 192];
        ss = sm2[tid] + sm2[tid + 64] + sm2[tid + 128] + sm2[tid + 192];
        atomicAdd(&g_S[c], s);
        atomicAdd(&g_SS[c], ss);
    }
}

// out[n] = dot(relu(y[n,:]), coef) + cnst, BN+linear fold computed inline.
__global__ void k_out(const float* __restrict__ gamma, const float* __restrict__ beta,
                      const float* __restrict__ lw, const float* __restrict__ lb,
                      float* __restrict__ out, int n) {
    int t = blockIdx.x * blockDim.x + threadIdx.x;
    int node = t >> 5;
    int j = t & 31;
    if (node >= n) return;
    float invn = 1.0f / (float)n;
    int j1 = j + 32;
    float m0 = g_S[j]  * invn,            m1 = g_S[j1] * invn;
    float v0 = g_SS[j] * invn - m0 * m0,  v1 = g_SS[j1] * invn - m1 * m1;
    float a0 = gamma[j]  * rsqrtf(v0 + 1e-5f);
    float a1 = gamma[j1] * rsqrtf(v1 + 1e-5f);
    float w0 = lw[j], w1 = lw[j1];
    float c0 = a0 * w0, c1 = a1 * w1;
    float part = (beta[j] - m0 * a0) * w0 + (beta[j1] - m1 * a1) * w1;
    float acc = fmaxf(g_y[node * HID + j],  0.f) * c0
              + fmaxf(g_y[node * HID + j1], 0.f) * c1
              + part;
#pragma unroll
    for (int o = 16; o > 0; o >>= 1) acc += __shfl_down_sync(0xffffffffu, acc, o);
    if (j == 0) out[node] = acc + lb[0];
}

// ---------------- launch ----------------
extern "C" void kernel_launch(void* const* d_in, const int* in_sizes, int n_in,
                              void* d_out, int out_size) {
    const float* x     = (const float*)d_in[0];
    const int*   ei    = (const int*)d_in[1];
    const float* ew    = (const float*)d_in[2];
    const float* Wz    = (const float*)d_in[3];
    const float* bz    = (const float*)d_in[4];
    const float* Wh    = (const float*)d_in[7];
    const float* bh    = (const float*)d_in[8];
    const float* gcn_w = (const float*)d_in[9];
    const float* gcn_b = (const float*)d_in[10];
    const float* gamma = (const float*)d_in[11];
    const float* beta  = (const float*)d_in[12];
    const float* lw    = (const float*)d_in[13];
    const float* lb    = (const float*)d_in[14];
    float* out = (float*)d_out;

    int n = in_sizes[0] / FEAT;
    int E = in_sizes[2];
    const int* row = ei;
    const int* col = ei + E;
    int NB = (n + 255) / 256;   // 196 tiles per array

    k_zero<<<(n + 255) / 256, 256>>>(n);
    k_wcat<<<(160 * 128 + 128 + 255) / 256, 256>>>(Wz, Wh, bz, bh);
    k_deg<<<(E + 255) / 256, 256>>>(row, col, ew, E);
    // parallel scan (replaces 146us 2-block k_scan)
    k_bsum<<<2 * NB, 256>>>(n, NB);
    k_bscan<<<1, 256>>>(NB);
    k_off<<<2 * NB, 256>>>(n, NB);     // also folds degree-inverse / dis
    k_fill<<<(E + 255) / 256, 256>>>(row, col, ew, E);
    // hop 1 (both dirs), hop 2 (both dirs) — pipelined atomic-free gathers
    k_spmm_g<<<(2 * n * 32 + 255) / 256, 256>>>(x, 1, n);
    k_spmm_g<<<(2 * n * 32 + 255) / 256, 256>>>(x, 2, n);
    // fused gates -> H
    k_gates<<<(n + 31) / 32, 128>>>(x, n);
    // GCN dense
    k_xw<<<(n + 31) / 32, 128>>>(gcn_w, n);
    // GCN gather (self term + bias fused)
    k_gcn_g<<<(n * 32 + 255) / 256, 256>>>(gcn_b, n);
    // BN stats + fused fold/output
    k_stats<<<512, 256>>>(n);
    k_out<<<(n * 32 + 255) / 256, 256>>>(gamma, beta, lw, lb, out, n);
}